// round 11
// baseline (speedup 1.0000x reference)
#include <cuda_runtime.h>
#include <cuda_bf16.h>
#include <cstdint>
#include <math.h>

#define VOCAB 100000
#define HID   128
#define BATCH 1024

// intermediate h_new (fp32) between the two kernels
__device__ float g_hnew[BATCH * HID];

__device__ __forceinline__ uint32_t f2tf32(float x) {
    uint32_t r;
    asm("cvt.rna.tf32.f32 %0, %1;" : "=r"(r) : "f"(x));
    return r;
}
__device__ __forceinline__ uint32_t smem_u32(const void* p) {
    uint32_t a;
    asm("{ .reg .u64 t; cvta.to.shared.u64 t, %1; cvt.u32.u64 %0, t; }"
        : "=r"(a) : "l"(p));
    return a;
}
__device__ __forceinline__ void cpa16(uint32_t dst, const void* src) {
    asm volatile("cp.async.cg.shared.global [%0], [%1], 16;"
                 :: "r"(dst), "l"(src) : "memory");
}
__device__ __forceinline__ void cpa_commit() {
    asm volatile("cp.async.commit_group;" ::: "memory");
}
__device__ __forceinline__ void cpa_wait1() {
    asm volatile("cp.async.wait_group 1;" ::: "memory");
}

// ---------------------------------------------------------------------------
// Kernel 1: GRU cell -> h_new  (128 CTAs x 384 thr, 8 batches per CTA)
// ---------------------------------------------------------------------------
#define BPB         8
#define GRU_THREADS 384
#define WHS_STRIDE  129   // odd stride: conflict-free phase-2 reads
#define GHS_STRIDE  9
#define GRU_SMEM    ((384 * WHS_STRIDE + 128 * BPB) * 4)   // 202,240 B

__global__ __launch_bounds__(GRU_THREADS, 1)
void gru_kernel(const int*   __restrict__ inp,
                const float* __restrict__ hid,
                const float* __restrict__ Wih,
                const float* __restrict__ bih,
                const float* __restrict__ Whh,
                const float* __restrict__ bhh,
                float*       __restrict__ out_hidden) {
    extern __shared__ float sm[];
    float* whs  = sm;                        // [384][129]
    float* h0sT = sm + 384 * WHS_STRIDE;     // [128 k][8 bl] (transposed)
    float* ghs  = sm;                        // overlay after phase 2: [384][9]

    const int tid = threadIdx.x;
    const int b0  = blockIdx.x * BPB;

    // Phase 1: stage W_hh (float4 loads, scalar STS) + transposed h0
#pragma unroll 4
    for (int i = 0; i < 32; i++) {
        int idx = tid + i * GRU_THREADS;     // 0..12287 float4 ids
        int j = idx >> 5, kq = (idx & 31) << 2;
        float4 w = *(const float4*)(Whh + j * HID + kq);
        float* d = whs + j * WHS_STRIDE + kq;
        d[0] = w.x; d[1] = w.y; d[2] = w.z; d[3] = w.w;
    }
    for (int idx = tid; idx < BPB * HID; idx += GRU_THREADS) {
        int bl = idx >> 7, k = idx & 127;
        h0sT[k * BPB + bl] = hid[(b0 + bl) * HID + k];
    }
    __syncthreads();

    // Phase 2: gh[b][j] = h0 . W_hh[j] + b_hh[j]; one j per thread, 8 batches
    const int j = tid;                       // 0..383
    float acc[BPB];
    {
        float bb = bhh[j];
#pragma unroll
        for (int u = 0; u < BPB; u++) acc[u] = bb;
        const float* wr = whs + j * WHS_STRIDE;
        for (int k = 0; k < HID; k++) {
            float  w  = wr[k];
            float4 h0 = *(const float4*)(h0sT + k * BPB);
            float4 h1 = *(const float4*)(h0sT + k * BPB + 4);
            acc[0] += h0.x * w;  acc[1] += h0.y * w;
            acc[2] += h0.z * w;  acc[3] += h0.w * w;
            acc[4] += h1.x * w;  acc[5] += h1.y * w;
            acc[6] += h1.z * w;  acc[7] += h1.w * w;
        }
    }
    __syncthreads();        // whs now dead
#pragma unroll
    for (int u = 0; u < BPB; u++)
        ghs[j * GHS_STRIDE + u] = acc[u];
    __syncthreads();

    // Phase 3: gates + h_new; gi via row-gather of W_ih at column input[b]
    for (int idx = tid; idx < BPB * HID; idx += GRU_THREADS) {
        int bl = idx >> 7, i = idx & 127;
        int b = b0 + bl;
        int v = inp[b];
        float gr  = Wih[(size_t)i * VOCAB + v]         + bih[i]       + ghs[i * GHS_STRIDE + bl];
        float gz  = Wih[(size_t)(i + 128) * VOCAB + v] + bih[i + 128] + ghs[(i + 128) * GHS_STRIDE + bl];
        float gin = Wih[(size_t)(i + 256) * VOCAB + v] + bih[i + 256];
        float ghn = ghs[(i + 256) * GHS_STRIDE + bl];
        float r = 1.f / (1.f + expf(-gr));
        float z = 1.f / (1.f + expf(-gz));
        float n = tanhf(gin + r * ghn);
        float h0v = h0sT[i * BPB + bl];
        float hn = (1.f - z) * n + z * h0v;
        g_hnew[b * HID + i]     = hn;
        out_hidden[b * HID + i] = hn;
    }
}

// ---------------------------------------------------------------------------
// Kernel 2: logits = ReLU(h_new @ W_out^T + b_out) via mma.sync tf32
//   Persistent CTAs (grid=148), each owns up to 43 consecutive tiles.
//   Tile 128x128x128; B double-buffered via cp.async; A restaged on mb change.
//   8 warps (4m x 2n), warp tile 32x64, m16n8k8; cvt to tf32 after LDS.
// ---------------------------------------------------------------------------
#define TSTR      132                                 // smem row stride (floats)
#define NB        ((VOCAB + 127) / 128)               // 782 n-tiles
#define TILES     (NB * 8)                            // 6256
#define GRID_G    148
#define CHUNK     ((TILES + GRID_G - 1) / GRID_G)     // 43
#define TILE_W    (128 * TSTR)                        // words per tile buffer
#define GEMM_SMEM (3 * TILE_W * 4)                    // 202,752 B

__device__ __forceinline__ void mma_tf32(float c[4],
                                         uint32_t a0, uint32_t a1, uint32_t a2, uint32_t a3,
                                         uint32_t b0, uint32_t b1) {
    asm volatile(
        "mma.sync.aligned.m16n8k8.row.col.f32.tf32.tf32.f32 "
        "{%0,%1,%2,%3}, {%4,%5,%6,%7}, {%8,%9}, {%0,%1,%2,%3};"
        : "+f"(c[0]), "+f"(c[1]), "+f"(c[2]), "+f"(c[3])
        : "r"(a0), "r"(a1), "r"(a2), "r"(a3), "r"(b0), "r"(b1));
}

// Prefetch B tile for tile-id t into buffer (raw fp32). Always commits a group.
__device__ __forceinline__ void prefetch_B(int t, int t_end,
                                           float* Bbuf, uint32_t Bbuf_a,
                                           const float* __restrict__ Wout, int tid) {
    if (t < t_end) {
        int nb = t % NB;
        int n0 = nb * 128;
#pragma unroll
        for (int i = 0; i < 16; i++) {
            int chunk = tid + (i << 8);        // 0..4095
            int r = chunk >> 5;                // row 0..127
            int q = chunk & 31;                // 16B chunk within row
            int n = n0 + r;
            if (n < VOCAB) {
                cpa16(Bbuf_a + (uint32_t)(r * (TSTR * 4) + q * 16),
                      Wout + (size_t)n * HID + q * 4);
            } else {
                *(float4*)(Bbuf + r * TSTR + q * 4) = make_float4(0.f, 0.f, 0.f, 0.f);
            }
        }
    }
    cpa_commit();
}

__global__ __launch_bounds__(256, 1)
void gemm_out_kernel(const float* __restrict__ Wout,
                     const float* __restrict__ bout,
                     float*       __restrict__ out) {
    extern __shared__ float smf[];
    float* As = smf;                         // [128][132] raw fp32
    float* Bb[2] = { smf + TILE_W, smf + 2 * TILE_W };
    const uint32_t sbase = smem_u32(smf);
    const uint32_t Bba[2] = { sbase + TILE_W * 4, sbase + 2 * TILE_W * 4 };

    const int tid = threadIdx.x;
    const int t0  = blockIdx.x * CHUNK;
    if (t0 >= TILES) return;
    const int t1  = min(t0 + CHUNK, TILES);

    const int w    = tid >> 5;
    const int lane = tid & 31;
    const int mw   = w >> 1;        // 0..3
    const int nw   = w & 1;         // 0..1
    const int g    = lane >> 2;     // 0..7
    const int t4   = lane & 3;      // 0..3

    // prologue: prefetch first two B tiles
    prefetch_B(t0,     t1, Bb[0], Bba[0], Wout, tid);
    prefetch_B(t0 + 1, t1, Bb[1], Bba[1], Wout, tid);

    int cur    = 0;
    int cur_mb = -1;

    for (int t = t0; t < t1; t++) {
        cpa_wait1();            // oldest pending group (buffer `cur`) complete
        __syncthreads();

        const int mb = t / NB;
        const int nb = t % NB;

        // (re)stage A on mb change — safe: all warps past previous compute
        if (mb != cur_mb) {
#pragma unroll
            for (int i = 0; i < 16; i++) {
                int idx = tid + (i << 8);
                int r  = idx >> 5;
                int kq = (idx & 31) << 2;
                float4 a = *(const float4*)(g_hnew + ((size_t)(mb * 128 + r) << 7) + kq);
                *(float4*)(As + r * TSTR + kq) = a;
            }
            cur_mb = mb;
            __syncthreads();
        }

        const float* Ap = As      + (mw * 32 + g) * TSTR + t4;
        const float* Bp = Bb[cur] + (nw * 64 + g) * TSTR + t4;

        float c[2][8][4];
#pragma unroll
        for (int mi = 0; mi < 2; mi++)
#pragma unroll
            for (int ni = 0; ni < 8; ni++)
#pragma unroll
                for (int q = 0; q < 4; q++) c[mi][ni][q] = 0.f;

#pragma unroll
        for (int ks = 0; ks < 16; ks++) {
            const int kb = ks * 8;
            uint32_t a[2][4], b[8][2];
#pragma unroll
            for (int mi = 0; mi < 2; mi++) {
                const float* p = Ap + mi * 16 * TSTR + kb;
                a[mi][0] = f2tf32(p[0]);
                a[mi][1] = f2tf32(p[8 * TSTR]);
                a[mi][2] = f2tf32(p[4]);
                a[mi][3] = f2tf32(p[8 * TSTR + 4]);
            }
#pragma unroll
            for (int ni = 0; ni < 8; ni++) {
                const float* p = Bp + ni * 8 * TSTR + kb;
                b[ni][0] = f2tf32(p[0]);
                b[ni][1] = f2tf32(p[4]);
            }
#pragma unroll
            for (int mi = 0; mi < 2; mi++)
#pragma unroll
                for (int ni = 0; ni < 8; ni++)
                    mma_tf32(c[mi][ni], a[mi][0], a[mi][1], a[mi][2], a[mi][3],
                             b[ni][0], b[ni][1]);
        }

        // epilogue: bias (+L2 __ldg) + ReLU, streaming float2 stores
#pragma unroll
        for (int mi = 0; mi < 2; mi++) {
            int row0 = mb * 128 + mw * 32 + mi * 16 + g;
            float* d0 = out + (size_t)row0 * VOCAB;
            float* d1 = d0 + 8 * VOCAB;
#pragma unroll
            for (int ni = 0; ni < 8; ni++) {
                int colb = nw * 64 + ni * 8 + 2 * t4;
                int col  = nb * 128 + colb;
                if (col < VOCAB) {
                    float2 bv = __ldg((const float2*)(bout + col));
                    float2 v0 = make_float2(fmaxf(c[mi][ni][0] + bv.x, 0.f),
                                            fmaxf(c[mi][ni][1] + bv.y, 0.f));
                    float2 v1 = make_float2(fmaxf(c[mi][ni][2] + bv.x, 0.f),
                                            fmaxf(c[mi][ni][3] + bv.y, 0.f));
                    __stcs((float2*)(d0 + col), v0);   // evict-first: keep W_out in L2
                    __stcs((float2*)(d1 + col), v1);
                }
            }
        }

        __syncthreads();        // all warps done reading Bb[cur]
        prefetch_B(t + 2, t1, Bb[cur], Bba[cur], Wout, tid);
        cur ^= 1;
    }
}

// ---------------------------------------------------------------------------
// launch
// ---------------------------------------------------------------------------
extern "C" void kernel_launch(void* const* d_in, const int* in_sizes, int n_in,
                              void* d_out, int out_size) {
    const int*   inp  = (const int*)  d_in[0];
    const float* hid  = (const float*)d_in[1];
    const float* Wih  = (const float*)d_in[2];
    const float* bih  = (const float*)d_in[3];
    const float* Whh  = (const float*)d_in[4];
    const float* bhh  = (const float*)d_in[5];
    const float* Wout = (const float*)d_in[6];
    const float* bout = (const float*)d_in[7];
    float* out = (float*)d_out;

    cudaFuncSetAttribute(gru_kernel, cudaFuncAttributeMaxDynamicSharedMemorySize, GRU_SMEM);
    cudaFuncSetAttribute(gemm_out_kernel, cudaFuncAttributeMaxDynamicSharedMemorySize, GEMM_SMEM);

    // output layout: [logits (1024 x 100000) | hidden (1 x 1024 x 128)]
    gru_kernel<<<BATCH / BPB, GRU_THREADS, GRU_SMEM>>>(
        inp, hid, Wih, bih, Whh, bhh, out + (size_t)BATCH * VOCAB);
    gemm_out_kernel<<<GRID_G, 256, GEMM_SMEM>>>(Wout, bout, out);
}

// round 12
// speedup vs baseline: 1.4078x; 1.4078x over previous
#include <cuda_runtime.h>
#include <cuda_bf16.h>
#include <cstdint>
#include <math.h>

#define VOCAB 100000
#define HID   128
#define BATCH 1024

// intermediate h_new (fp32) between the two kernels
__device__ float g_hnew[BATCH * HID];

__device__ __forceinline__ uint32_t f2tf32(float x) {
    uint32_t r;
    asm("cvt.rna.tf32.f32 %0, %1;" : "=r"(r) : "f"(x));
    return r;
}
__device__ __forceinline__ uint32_t smem_u32(const void* p) {
    uint32_t a;
    asm("{ .reg .u64 t; cvta.to.shared.u64 t, %1; cvt.u32.u64 %0, t; }"
        : "=r"(a) : "l"(p));
    return a;
}
__device__ __forceinline__ void cpa16(uint32_t dst, const void* src) {
    asm volatile("cp.async.cg.shared.global [%0], [%1], 16;"
                 :: "r"(dst), "l"(src) : "memory");
}
__device__ __forceinline__ void cpa_commit() {
    asm volatile("cp.async.commit_group;" ::: "memory");
}
__device__ __forceinline__ void cpa_wait1() {
    asm volatile("cp.async.wait_group 1;" ::: "memory");
}
__device__ __forceinline__ void ldsm4(uint32_t r[4], uint32_t addr) {
    asm volatile("ldmatrix.sync.aligned.m8n8.x4.shared.b16 {%0,%1,%2,%3}, [%4];"
                 : "=r"(r[0]), "=r"(r[1]), "=r"(r[2]), "=r"(r[3]) : "r"(addr));
}

// ---------------------------------------------------------------------------
// Kernel 1: GRU cell -> h_new  (128 CTAs x 384 thr, 8 batches per CTA)
// ---------------------------------------------------------------------------
#define BPB         8
#define GRU_THREADS 384
#define WHS_STRIDE  129
#define GHS_STRIDE  9
#define GRU_SMEM    ((384 * WHS_STRIDE + 128 * BPB) * 4)   // 202,240 B

__global__ __launch_bounds__(GRU_THREADS, 1)
void gru_kernel(const int*   __restrict__ inp,
                const float* __restrict__ hid,
                const float* __restrict__ Wih,
                const float* __restrict__ bih,
                const float* __restrict__ Whh,
                const float* __restrict__ bhh,
                float*       __restrict__ out_hidden) {
    extern __shared__ float sm[];
    float* whs  = sm;                        // [384][129]
    float* h0sT = sm + 384 * WHS_STRIDE;     // [128 k][8 bl]
    float* ghs  = sm;                        // overlay after phase 2: [384][9]

    const int tid = threadIdx.x;
    const int b0  = blockIdx.x * BPB;

#pragma unroll 4
    for (int i = 0; i < 32; i++) {
        int idx = tid + i * GRU_THREADS;
        int j = idx >> 5, kq = (idx & 31) << 2;
        float4 w = *(const float4*)(Whh + j * HID + kq);
        float* d = whs + j * WHS_STRIDE + kq;
        d[0] = w.x; d[1] = w.y; d[2] = w.z; d[3] = w.w;
    }
    for (int idx = tid; idx < BPB * HID; idx += GRU_THREADS) {
        int bl = idx >> 7, k = idx & 127;
        h0sT[k * BPB + bl] = hid[(b0 + bl) * HID + k];
    }
    __syncthreads();

    const int j = tid;                       // 0..383
    float acc[BPB];
    {
        float bb = bhh[j];
#pragma unroll
        for (int u = 0; u < BPB; u++) acc[u] = bb;
        const float* wr = whs + j * WHS_STRIDE;
        for (int k = 0; k < HID; k++) {
            float  w  = wr[k];
            float4 h0 = *(const float4*)(h0sT + k * BPB);
            float4 h1 = *(const float4*)(h0sT + k * BPB + 4);
            acc[0] += h0.x * w;  acc[1] += h0.y * w;
            acc[2] += h0.z * w;  acc[3] += h0.w * w;
            acc[4] += h1.x * w;  acc[5] += h1.y * w;
            acc[6] += h1.z * w;  acc[7] += h1.w * w;
        }
    }
    __syncthreads();
#pragma unroll
    for (int u = 0; u < BPB; u++)
        ghs[j * GHS_STRIDE + u] = acc[u];
    __syncthreads();

    for (int idx = tid; idx < BPB * HID; idx += GRU_THREADS) {
        int bl = idx >> 7, i = idx & 127;
        int b = b0 + bl;
        int v = inp[b];
        float gr  = Wih[(size_t)i * VOCAB + v]         + bih[i]       + ghs[i * GHS_STRIDE + bl];
        float gz  = Wih[(size_t)(i + 128) * VOCAB + v] + bih[i + 128] + ghs[(i + 128) * GHS_STRIDE + bl];
        float gin = Wih[(size_t)(i + 256) * VOCAB + v] + bih[i + 256];
        float ghn = ghs[(i + 256) * GHS_STRIDE + bl];
        float r = 1.f / (1.f + expf(-gr));
        float z = 1.f / (1.f + expf(-gz));
        float n = tanhf(gin + r * ghn);
        float h0v = h0sT[i * BPB + bl];
        float hn = (1.f - z) * n + z * h0v;
        g_hnew[b * HID + i]     = hn;
        out_hidden[b * HID + i] = hn;
    }
}

// ---------------------------------------------------------------------------
// Kernel 2: logits = ReLU(h_new @ W_out^T + b_out) via mma.sync tf32
//   Persistent (grid=148), 512 thr / 16 warps, warp grid 4m x 4n, warp 32x32
//   B double-buffered cp.async (raw fp32, cvt after ldmatrix);
//   A staged once per mb as tf32 bits; fragments via ldmatrix.x4.
// ---------------------------------------------------------------------------
#define TSTR      132                                 // smem row stride (floats)
#define NB        ((VOCAB + 127) / 128)               // 782 n-tiles
#define TILES     (NB * 8)                            // 6256
#define GRID_G    148
#define CHUNK     ((TILES + GRID_G - 1) / GRID_G)     // 43
#define TILE_W    (128 * TSTR)
#define GEMM_SMEM (3 * TILE_W * 4)                    // 202,752 B

__device__ __forceinline__ void mma_tf32(float c[4],
                                         uint32_t a0, uint32_t a1, uint32_t a2, uint32_t a3,
                                         uint32_t b0, uint32_t b1) {
    asm volatile(
        "mma.sync.aligned.m16n8k8.row.col.f32.tf32.tf32.f32 "
        "{%0,%1,%2,%3}, {%4,%5,%6,%7}, {%8,%9}, {%0,%1,%2,%3};"
        : "+f"(c[0]), "+f"(c[1]), "+f"(c[2]), "+f"(c[3])
        : "r"(a0), "r"(a1), "r"(a2), "r"(a3), "r"(b0), "r"(b1));
}

// Prefetch B tile t (raw fp32) into buffer. Always commits a group.
__device__ __forceinline__ void prefetch_B(int t, int t_end,
                                           float* Bbuf, uint32_t Bbuf_a,
                                           const float* __restrict__ Wout, int tid) {
    if (t < t_end) {
        int n0 = (t % NB) * 128;
#pragma unroll
        for (int i = 0; i < 8; i++) {
            int chunk = tid + (i << 9);        // 0..4095
            int r = chunk >> 5;
            int q = chunk & 31;
            int n = n0 + r;
            if (n < VOCAB) {
                cpa16(Bbuf_a + (uint32_t)(r * (TSTR * 4) + q * 16),
                      Wout + (size_t)n * HID + q * 4);
            } else {
                *(float4*)(Bbuf + r * TSTR + q * 4) = make_float4(0.f, 0.f, 0.f, 0.f);
            }
        }
    }
    cpa_commit();
}

__global__ __launch_bounds__(512, 1)
void gemm_out_kernel(const float* __restrict__ Wout,
                     const float* __restrict__ bout,
                     float*       __restrict__ out) {
    extern __shared__ float smf[];
    float* Bb[2] = { smf + TILE_W, smf + 2 * TILE_W };
    uint32_t* As = (uint32_t*)smf;                 // tf32 bits
    const uint32_t sbase  = smem_u32(smf);
    const uint32_t Bba[2] = { sbase + TILE_W * 4, sbase + 2 * TILE_W * 4 };

    const int tid = threadIdx.x;
    const int t0  = blockIdx.x * CHUNK;
    if (t0 >= TILES) return;
    const int t1  = min(t0 + CHUNK, TILES);

    const int w    = tid >> 5;
    const int lane = tid & 31;
    const int mw   = w >> 2;        // 0..3
    const int nw   = w & 3;         // 0..3
    const int g    = lane >> 2;     // 0..7
    const int t4   = lane & 3;      // 0..3
    const int lr   = lane & 7;
    const int s1   = (lane >> 3) & 1;
    const int s2   = (lane >> 4) & 1;

    // ldmatrix per-lane addresses
    // A: row += 8*s1, col(+4 floats) via s2
    uint32_t aAdr[2];
#pragma unroll
    for (int mi = 0; mi < 2; mi++)
        aAdr[mi] = sbase + 4u * ((mw * 32 + mi * 16 + lr + 8 * s1) * TSTR + 4 * s2);
    // B: n-block += s2, col(+4 floats) via s1  (byte offset within a B buffer)
    uint32_t bOff[2];
#pragma unroll
    for (int p = 0; p < 2; p++)
        bOff[p] = 4u * ((nw * 32 + (2 * p + s2) * 8 + lr) * TSTR + 4 * s1);

    // prologue: prefetch first two B tiles
    prefetch_B(t0,     t1, Bb[0], Bba[0], Wout, tid);
    prefetch_B(t0 + 1, t1, Bb[1], Bba[1], Wout, tid);

    int cur    = 0;
    int cur_mb = -1;

    for (int t = t0; t < t1; t++) {
        cpa_wait1();
        __syncthreads();

        const int mb = t / NB;
        const int nb = t % NB;

        if (mb != cur_mb) {     // stage A as tf32 bits (rare: <=2x per CTA)
#pragma unroll
            for (int i = 0; i < 8; i++) {
                int idx = tid + (i << 9);
                int r  = idx >> 5;
                int kq = (idx & 31) << 2;
                float4 a = *(const float4*)(g_hnew + ((size_t)(mb * 128 + r) << 7) + kq);
                *(uint4*)(As + r * TSTR + kq) =
                    make_uint4(f2tf32(a.x), f2tf32(a.y), f2tf32(a.z), f2tf32(a.w));
            }
            cur_mb = mb;
            __syncthreads();
        }

        const uint32_t bb = Bba[cur] - sbase;   // 0 or 2*TILE_W*4 ... relative add

        float c[2][4][4];
#pragma unroll
        for (int mi = 0; mi < 2; mi++)
#pragma unroll
            for (int ni = 0; ni < 4; ni++)
#pragma unroll
                for (int q = 0; q < 4; q++) c[mi][ni][q] = 0.f;

#pragma unroll
        for (int ks = 0; ks < 16; ks++) {
            uint32_t A0[4], A1[4], B0[4], B1[4];
            ldsm4(A0, aAdr[0] + ks * 32);
            ldsm4(A1, aAdr[1] + ks * 32);
            ldsm4(B0, sbase + bb + bOff[0] + ks * 32);
            ldsm4(B1, sbase + bb + bOff[1] + ks * 32);
#pragma unroll
            for (int q = 0; q < 4; q++) {
                B0[q] = f2tf32(__uint_as_float(B0[q]));
                B1[q] = f2tf32(__uint_as_float(B1[q]));
            }
            mma_tf32(c[0][0], A0[0], A0[1], A0[2], A0[3], B0[0], B0[1]);
            mma_tf32(c[0][1], A0[0], A0[1], A0[2], A0[3], B0[2], B0[3]);
            mma_tf32(c[0][2], A0[0], A0[1], A0[2], A0[3], B1[0], B1[1]);
            mma_tf32(c[0][3], A0[0], A0[1], A0[2], A0[3], B1[2], B1[3]);
            mma_tf32(c[1][0], A1[0], A1[1], A1[2], A1[3], B0[0], B0[1]);
            mma_tf32(c[1][1], A1[0], A1[1], A1[2], A1[3], B0[2], B0[3]);
            mma_tf32(c[1][2], A1[0], A1[1], A1[2], A1[3], B1[0], B1[1]);
            mma_tf32(c[1][3], A1[0], A1[1], A1[2], A1[3], B1[2], B1[3]);
        }

        // all warps done with Bb[cur]: start prefetch for t+2, then epilogue
        __syncthreads();
        prefetch_B(t + 2, t1, Bb[cur], Bba[cur], Wout, tid);

#pragma unroll
        for (int mi = 0; mi < 2; mi++) {
            int row0 = mb * 128 + mw * 32 + mi * 16 + g;
            float* d0 = out + (size_t)row0 * VOCAB;
            float* d1 = d0 + 8 * VOCAB;
#pragma unroll
            for (int ni = 0; ni < 4; ni++) {
                int col = nb * 128 + nw * 32 + ni * 8 + 2 * t4;
                if (col < VOCAB) {
                    float2 bv = __ldg((const float2*)(bout + col));
                    float2 v0 = make_float2(fmaxf(c[mi][ni][0] + bv.x, 0.f),
                                            fmaxf(c[mi][ni][1] + bv.y, 0.f));
                    float2 v1 = make_float2(fmaxf(c[mi][ni][2] + bv.x, 0.f),
                                            fmaxf(c[mi][ni][3] + bv.y, 0.f));
                    __stcs((float2*)(d0 + col), v0);   // evict-first: keep W_out in L2
                    __stcs((float2*)(d1 + col), v1);
                }
            }
        }
        cur ^= 1;
    }
}

// ---------------------------------------------------------------------------
// launch
// ---------------------------------------------------------------------------
extern "C" void kernel_launch(void* const* d_in, const int* in_sizes, int n_in,
                              void* d_out, int out_size) {
    const int*   inp  = (const int*)  d_in[0];
    const float* hid  = (const float*)d_in[1];
    const float* Wih  = (const float*)d_in[2];
    const float* bih  = (const float*)d_in[3];
    const float* Whh  = (const float*)d_in[4];
    const float* bhh  = (const float*)d_in[5];
    const float* Wout = (const float*)d_in[6];
    const float* bout = (const float*)d_in[7];
    float* out = (float*)d_out;

    cudaFuncSetAttribute(gru_kernel, cudaFuncAttributeMaxDynamicSharedMemorySize, GRU_SMEM);
    cudaFuncSetAttribute(gemm_out_kernel, cudaFuncAttributeMaxDynamicSharedMemorySize, GEMM_SMEM);

    // output layout: [logits (1024 x 100000) | hidden (1 x 1024 x 128)]
    gru_kernel<<<BATCH / BPB, GRU_THREADS, GRU_SMEM>>>(
        inp, hid, Wih, bih, Whh, bhh, out + (size_t)BATCH * VOCAB);
    gemm_out_kernel<<<GRID_G, 512, GEMM_SMEM>>>(Wout, bout, out);
}

// round 14
// speedup vs baseline: 1.4753x; 1.0479x over previous
#include <cuda_runtime.h>
#include <cuda_bf16.h>
#include <cstdint>
#include <math.h>

#define VOCAB 100000
#define HID   128
#define BATCH 1024

// intermediate h_new (fp32) between the two kernels
__device__ float g_hnew[BATCH * HID];

__device__ __forceinline__ uint32_t f2tf32(float x) {
    uint32_t r;
    asm("cvt.rna.tf32.f32 %0, %1;" : "=r"(r) : "f"(x));
    return r;
}
__device__ __forceinline__ uint32_t smem_u32(const void* p) {
    uint32_t a;
    asm("{ .reg .u64 t; cvta.to.shared.u64 t, %1; cvt.u32.u64 %0, t; }"
        : "=r"(a) : "l"(p));
    return a;
}
__device__ __forceinline__ void cpa16(uint32_t dst, const void* src) {
    asm volatile("cp.async.cg.shared.global [%0], [%1], 16;"
                 :: "r"(dst), "l"(src) : "memory");
}
__device__ __forceinline__ void cpa_commit() {
    asm volatile("cp.async.commit_group;" ::: "memory");
}
__device__ __forceinline__ void cpa_wait1() {
    asm volatile("cp.async.wait_group 1;" ::: "memory");
}
__device__ __forceinline__ void ldsm4(uint32_t r[4], uint32_t addr) {
    asm volatile("ldmatrix.sync.aligned.m8n8.x4.shared.b16 {%0,%1,%2,%3}, [%4];"
                 : "=r"(r[0]), "=r"(r[1]), "=r"(r[2]), "=r"(r[3]) : "r"(addr));
}

// ---------------------------------------------------------------------------
// Kernel 1: GRU cell -> h_new  (128 CTAs x 384 thr, 8 batches per CTA)
// ---------------------------------------------------------------------------
#define BPB         8
#define GRU_THREADS 384
#define WHS_STRIDE  129
#define GHS_STRIDE  9
#define GRU_SMEM    ((384 * WHS_STRIDE + 128 * BPB) * 4)   // 202,240 B

__global__ __launch_bounds__(GRU_THREADS, 1)
void gru_kernel(const int*   __restrict__ inp,
                const float* __restrict__ hid,
                const float* __restrict__ Wih,
                const float* __restrict__ bih,
                const float* __restrict__ Whh,
                const float* __restrict__ bhh,
                float*       __restrict__ out_hidden) {
    extern __shared__ float sm[];
    float* whs  = sm;                        // [384][129]
    float* h0sT = sm + 384 * WHS_STRIDE;     // [128 k][8 bl]
    float* ghs  = sm;                        // overlay after phase 2: [384][9]

    const int tid = threadIdx.x;
    const int b0  = blockIdx.x * BPB;

#pragma unroll 4
    for (int i = 0; i < 32; i++) {
        int idx = tid + i * GRU_THREADS;
        int j = idx >> 5, kq = (idx & 31) << 2;
        float4 w = *(const float4*)(Whh + j * HID + kq);
        float* d = whs + j * WHS_STRIDE + kq;
        d[0] = w.x; d[1] = w.y; d[2] = w.z; d[3] = w.w;
    }
    for (int idx = tid; idx < BPB * HID; idx += GRU_THREADS) {
        int bl = idx >> 7, k = idx & 127;
        h0sT[k * BPB + bl] = hid[(b0 + bl) * HID + k];
    }
    __syncthreads();

    const int j = tid;                       // 0..383
    float acc[BPB];
    {
        float bb = bhh[j];
#pragma unroll
        for (int u = 0; u < BPB; u++) acc[u] = bb;
        const float* wr = whs + j * WHS_STRIDE;
        for (int k = 0; k < HID; k++) {
            float  w  = wr[k];
            float4 h0 = *(const float4*)(h0sT + k * BPB);
            float4 h1 = *(const float4*)(h0sT + k * BPB + 4);
            acc[0] += h0.x * w;  acc[1] += h0.y * w;
            acc[2] += h0.z * w;  acc[3] += h0.w * w;
            acc[4] += h1.x * w;  acc[5] += h1.y * w;
            acc[6] += h1.z * w;  acc[7] += h1.w * w;
        }
    }
    __syncthreads();
#pragma unroll
    for (int u = 0; u < BPB; u++)
        ghs[j * GHS_STRIDE + u] = acc[u];
    __syncthreads();

    for (int idx = tid; idx < BPB * HID; idx += GRU_THREADS) {
        int bl = idx >> 7, i = idx & 127;
        int b = b0 + bl;
        int v = inp[b];
        float gr  = Wih[(size_t)i * VOCAB + v]         + bih[i]       + ghs[i * GHS_STRIDE + bl];
        float gz  = Wih[(size_t)(i + 128) * VOCAB + v] + bih[i + 128] + ghs[(i + 128) * GHS_STRIDE + bl];
        float gin = Wih[(size_t)(i + 256) * VOCAB + v] + bih[i + 256];
        float ghn = ghs[(i + 256) * GHS_STRIDE + bl];
        float r = 1.f / (1.f + expf(-gr));
        float z = 1.f / (1.f + expf(-gz));
        float n = tanhf(gin + r * ghn);
        float h0v = h0sT[i * BPB + bl];
        float hn = (1.f - z) * n + z * h0v;
        g_hnew[b * HID + i]     = hn;
        out_hidden[b * HID + i] = hn;
    }
}

// ---------------------------------------------------------------------------
// Kernel 2: logits = ReLU(h_new @ W_out^T + b_out) via mma.sync tf32
//   Persistent (grid=148), 512 thr / 16 warps, warp grid 4m x 4n, warp 32x32
//   B double-buffered cp.async, used RAW (tf32 HW truncation, no cvt);
//   A staged once per mb as RNA tf32 bits; fragments via ldmatrix.x4,
//   software-pipelined (prefetch ks+1 before MMAs of ks).
// ---------------------------------------------------------------------------
#define TSTR      132                                 // smem row stride (floats)
#define NB        ((VOCAB + 127) / 128)               // 782 n-tiles
#define TILES     (NB * 8)                            // 6256
#define GRID_G    148
#define CHUNK     ((TILES + GRID_G - 1) / GRID_G)     // 43
#define TILE_W    (128 * TSTR)
#define GEMM_SMEM (3 * TILE_W * 4)                    // 202,752 B

__device__ __forceinline__ void mma_tf32(float c[4],
                                         uint32_t a0, uint32_t a1, uint32_t a2, uint32_t a3,
                                         uint32_t b0, uint32_t b1) {
    asm volatile(
        "mma.sync.aligned.m16n8k8.row.col.f32.tf32.tf32.f32 "
        "{%0,%1,%2,%3}, {%4,%5,%6,%7}, {%8,%9}, {%0,%1,%2,%3};"
        : "+f"(c[0]), "+f"(c[1]), "+f"(c[2]), "+f"(c[3])
        : "r"(a0), "r"(a1), "r"(a2), "r"(a3), "r"(b0), "r"(b1));
}

// Prefetch B tile t (raw fp32) into buffer. Always commits a group.
__device__ __forceinline__ void prefetch_B(int t, int t_end,
                                           float* Bbuf, uint32_t Bbuf_a,
                                           const float* __restrict__ Wout, int tid) {
    if (t < t_end) {
        int n0 = (t % NB) * 128;
#pragma unroll
        for (int i = 0; i < 8; i++) {
            int chunk = tid + (i << 9);        // 0..4095
            int r = chunk >> 5;
            int q = chunk & 31;
            int n = n0 + r;
            if (n < VOCAB) {
                cpa16(Bbuf_a + (uint32_t)(r * (TSTR * 4) + q * 16),
                      Wout + (size_t)n * HID + q * 4);
            } else {
                *(float4*)(Bbuf + r * TSTR + q * 4) = make_float4(0.f, 0.f, 0.f, 0.f);
            }
        }
    }
    cpa_commit();
}

__global__ __launch_bounds__(512, 1)
void gemm_out_kernel(const float* __restrict__ Wout,
                     const float* __restrict__ bout,
                     float*       __restrict__ out) {
    extern __shared__ float smf[];
    float* Bb[2] = { smf + TILE_W, smf + 2 * TILE_W };
    uint32_t* As = (uint32_t*)smf;                 // tf32 bits (RNA)
    const uint32_t sbase  = smem_u32(smf);
    const uint32_t Bba[2] = { sbase + TILE_W * 4, sbase + 2 * TILE_W * 4 };

    const int tid = threadIdx.x;
    const int t0  = blockIdx.x * CHUNK;
    if (t0 >= TILES) return;
    const int t1  = min(t0 + CHUNK, TILES);

    const int w    = tid >> 5;
    const int lane = tid & 31;
    const int mw   = w >> 2;        // 0..3
    const int nw   = w & 3;         // 0..3
    const int g    = lane >> 2;     // 0..7
    const int t4   = lane & 3;      // 0..3
    const int lr   = lane & 7;
    const int s1   = (lane >> 3) & 1;
    const int s2   = (lane >> 4) & 1;

    // ldmatrix per-lane addresses
    uint32_t aAdr0 = sbase + 4u * ((mw * 32 +      lr + 8 * s1) * TSTR + 4 * s2);
    uint32_t aAdr1 = sbase + 4u * ((mw * 32 + 16 + lr + 8 * s1) * TSTR + 4 * s2);
    uint32_t bOff0 = 4u * ((nw * 32 + s2 * 8 + lr) * TSTR + 4 * s1);
    uint32_t bOff1 = 4u * ((nw * 32 + (2 + s2) * 8 + lr) * TSTR + 4 * s1);

    // prologue: prefetch first two B tiles
    prefetch_B(t0,     t1, Bb[0], Bba[0], Wout, tid);
    prefetch_B(t0 + 1, t1, Bb[1], Bba[1], Wout, tid);

    int cur    = 0;
    int cur_mb = -1;

    for (int t = t0; t < t1; t++) {
        cpa_wait1();
        __syncthreads();

        const int mb = t / NB;
        const int nb = t % NB;

        if (mb != cur_mb) {     // stage A as RNA tf32 bits (<=2x per CTA)
#pragma unroll
            for (int i = 0; i < 8; i++) {
                int idx = tid + (i << 9);
                int r  = idx >> 5;
                int kq = (idx & 31) << 2;
                float4 a = *(const float4*)(g_hnew + ((size_t)(mb * 128 + r) << 7) + kq);
                *(uint4*)(As + r * TSTR + kq) =
                    make_uint4(f2tf32(a.x), f2tf32(a.y), f2tf32(a.z), f2tf32(a.w));
            }
            cur_mb = mb;
            __syncthreads();
        }

        const uint32_t bAdr0 = Bba[cur] + bOff0;
        const uint32_t bAdr1 = Bba[cur] + bOff1;

        float c[2][4][4];
#pragma unroll
        for (int mi = 0; mi < 2; mi++)
#pragma unroll
            for (int ni = 0; ni < 4; ni++)
#pragma unroll
                for (int q = 0; q < 4; q++) c[mi][ni][q] = 0.f;

        // software-pipelined mainloop: fragments for ks+1 loaded before MMAs of ks
        uint32_t A0[2][4], A1[2][4], B0[2][4], B1[2][4];
        ldsm4(A0[0], aAdr0);
        ldsm4(A1[0], aAdr1);
        ldsm4(B0[0], bAdr0);
        ldsm4(B1[0], bAdr1);
#pragma unroll
        for (int ks = 0; ks < 16; ks++) {
            const int pb = ks & 1;
            const int nx = pb ^ 1;
            if (ks < 15) {
                const uint32_t d = (ks + 1) * 32;
                ldsm4(A0[nx], aAdr0 + d);
                ldsm4(A1[nx], aAdr1 + d);
                ldsm4(B0[nx], bAdr0 + d);
                ldsm4(B1[nx], bAdr1 + d);
            }
            mma_tf32(c[0][0], A0[pb][0], A0[pb][1], A0[pb][2], A0[pb][3], B0[pb][0], B0[pb][1]);
            mma_tf32(c[0][1], A0[pb][0], A0[pb][1], A0[pb][2], A0[pb][3], B0[pb][2], B0[pb][3]);
            mma_tf32(c[0][2], A0[pb][0], A0[pb][1], A0[pb][2], A0[pb][3], B1[pb][0], B1[pb][1]);
            mma_tf32(c[0][3], A0[pb][0], A0[pb][1], A0[pb][2], A0[pb][3], B1[pb][2], B1[pb][3]);
            mma_tf32(c[1][0], A1[pb][0], A1[pb][1], A1[pb][2], A1[pb][3], B0[pb][0], B0[pb][1]);
            mma_tf32(c[1][1], A1[pb][0], A1[pb][1], A1[pb][2], A1[pb][3], B0[pb][2], B0[pb][3]);
            mma_tf32(c[1][2], A1[pb][0], A1[pb][1], A1[pb][2], A1[pb][3], B1[pb][0], B1[pb][1]);
            mma_tf32(c[1][3], A1[pb][0], A1[pb][1], A1[pb][2], A1[pb][3], B1[pb][2], B1[pb][3]);
        }

        // all warps done with Bb[cur]: start prefetch for t+2, then epilogue
        __syncthreads();
        prefetch_B(t + 2, t1, Bb[cur], Bba[cur], Wout, tid);

#pragma unroll
        for (int mi = 0; mi < 2; mi++) {
            int row0 = mb * 128 + mw * 32 + mi * 16 + g;
            float* d0 = out + (size_t)row0 * VOCAB;
            float* d1 = d0 + 8 * VOCAB;
#pragma unroll
            for (int ni = 0; ni < 4; ni++) {
                int col = nb * 128 + nw * 32 + ni * 8 + 2 * t4;
                if (col < VOCAB) {
                    float2 bv = __ldg((const float2*)(bout + col));
                    float2 v0 = make_float2(fmaxf(c[mi][ni][0] + bv.x, 0.f),
                                            fmaxf(c[mi][ni][1] + bv.y, 0.f));
                    float2 v1 = make_float2(fmaxf(c[mi][ni][2] + bv.x, 0.f),
                                            fmaxf(c[mi][ni][3] + bv.y, 0.f));
                    __stcs((float2*)(d0 + col), v0);   // evict-first: keep W_out in L2
                    __stcs((float2*)(d1 + col), v1);
                }
            }
        }
        cur ^= 1;
    }
}

// ---------------------------------------------------------------------------
// launch
// ---------------------------------------------------------------------------
extern "C" void kernel_launch(void* const* d_in, const int* in_sizes, int n_in,
                              void* d_out, int out_size) {
    const int*   inp  = (const int*)  d_in[0];
    const float* hid  = (const float*)d_in[1];
    const float* Wih  = (const float*)d_in[2];
    const float* bih  = (const float*)d_in[3];
    const float* Whh  = (const float*)d_in[4];
    const float* bhh  = (const float*)d_in[5];
    const float* Wout = (const float*)d_in[6];
    const float* bout = (const float*)d_in[7];
    float* out = (float*)d_out;

    cudaFuncSetAttribute(gru_kernel, cudaFuncAttributeMaxDynamicSharedMemorySize, GRU_SMEM);
    cudaFuncSetAttribute(gemm_out_kernel, cudaFuncAttributeMaxDynamicSharedMemorySize, GEMM_SMEM);

    // output layout: [logits (1024 x 100000) | hidden (1 x 1024 x 128)]
    gru_kernel<<<BATCH / BPB, GRU_THREADS, GRU_SMEM>>>(
        inp, hid, Wih, bih, Whh, bhh, out + (size_t)BATCH * VOCAB);
    gemm_out_kernel<<<GRID_G, 512, GEMM_SMEM>>>(Wout, bout, out);
}

// round 15
// speedup vs baseline: 1.5576x; 1.0558x over previous
#include <cuda_runtime.h>
#include <cuda_bf16.h>
#include <cstdint>
#include <math.h>

#define VOCAB 100000
#define HID   128
#define BATCH 1024

// intermediate h_new (fp32) between the two kernels
__device__ float g_hnew[BATCH * HID];

__device__ __forceinline__ uint32_t f2tf32(float x) {
    uint32_t r;
    asm("cvt.rna.tf32.f32 %0, %1;" : "=r"(r) : "f"(x));
    return r;
}
__device__ __forceinline__ uint32_t smem_u32(const void* p) {
    uint32_t a;
    asm("{ .reg .u64 t; cvta.to.shared.u64 t, %1; cvt.u32.u64 %0, t; }"
        : "=r"(a) : "l"(p));
    return a;
}
__device__ __forceinline__ void cpa16(uint32_t dst, const void* src) {
    asm volatile("cp.async.cg.shared.global [%0], [%1], 16;"
                 :: "r"(dst), "l"(src) : "memory");
}
__device__ __forceinline__ void cpa_commit() {
    asm volatile("cp.async.commit_group;" ::: "memory");
}
__device__ __forceinline__ void cpa_wait1() {
    asm volatile("cp.async.wait_group 1;" ::: "memory");
}
__device__ __forceinline__ void ldsm4(uint32_t r[4], uint32_t addr) {
    asm volatile("ldmatrix.sync.aligned.m8n8.x4.shared.b16 {%0,%1,%2,%3}, [%4];"
                 : "=r"(r[0]), "=r"(r[1]), "=r"(r[2]), "=r"(r[3]) : "r"(addr));
}

// ---------------------------------------------------------------------------
// Kernel 1: GRU cell -> h_new  (128 CTAs x 384 thr, 8 batches per CTA)
// ---------------------------------------------------------------------------
#define BPB         8
#define GRU_THREADS 384
#define WHS_STRIDE  129
#define GHS_STRIDE  9
#define GRU_SMEM    ((384 * WHS_STRIDE + 128 * BPB) * 4)   // 202,240 B

__global__ __launch_bounds__(GRU_THREADS, 1)
void gru_kernel(const int*   __restrict__ inp,
                const float* __restrict__ hid,
                const float* __restrict__ Wih,
                const float* __restrict__ bih,
                const float* __restrict__ Whh,
                const float* __restrict__ bhh,
                float*       __restrict__ out_hidden) {
    extern __shared__ float sm[];
    float* whs  = sm;                        // [384][129]
    float* h0sT = sm + 384 * WHS_STRIDE;     // [128 k][8 bl]
    float* ghs  = sm;                        // overlay after phase 2: [384][9]

    const int tid = threadIdx.x;
    const int b0  = blockIdx.x * BPB;

#pragma unroll 4
    for (int i = 0; i < 32; i++) {
        int idx = tid + i * GRU_THREADS;
        int j = idx >> 5, kq = (idx & 31) << 2;
        float4 w = *(const float4*)(Whh + j * HID + kq);
        float* d = whs + j * WHS_STRIDE + kq;
        d[0] = w.x; d[1] = w.y; d[2] = w.z; d[3] = w.w;
    }
    for (int idx = tid; idx < BPB * HID; idx += GRU_THREADS) {
        int bl = idx >> 7, k = idx & 127;
        h0sT[k * BPB + bl] = hid[(b0 + bl) * HID + k];
    }
    __syncthreads();

    const int j = tid;                       // 0..383
    float acc[BPB];
    {
        float bb = bhh[j];
#pragma unroll
        for (int u = 0; u < BPB; u++) acc[u] = bb;
        const float* wr = whs + j * WHS_STRIDE;
        for (int k = 0; k < HID; k++) {
            float  w  = wr[k];
            float4 h0 = *(const float4*)(h0sT + k * BPB);
            float4 h1 = *(const float4*)(h0sT + k * BPB + 4);
            acc[0] += h0.x * w;  acc[1] += h0.y * w;
            acc[2] += h0.z * w;  acc[3] += h0.w * w;
            acc[4] += h1.x * w;  acc[5] += h1.y * w;
            acc[6] += h1.z * w;  acc[7] += h1.w * w;
        }
    }
    __syncthreads();
#pragma unroll
    for (int u = 0; u < BPB; u++)
        ghs[j * GHS_STRIDE + u] = acc[u];
    __syncthreads();

    for (int idx = tid; idx < BPB * HID; idx += GRU_THREADS) {
        int bl = idx >> 7, i = idx & 127;
        int b = b0 + bl;
        int v = inp[b];
        float gr  = Wih[(size_t)i * VOCAB + v]         + bih[i]       + ghs[i * GHS_STRIDE + bl];
        float gz  = Wih[(size_t)(i + 128) * VOCAB + v] + bih[i + 128] + ghs[(i + 128) * GHS_STRIDE + bl];
        float gin = Wih[(size_t)(i + 256) * VOCAB + v] + bih[i + 256];
        float ghn = ghs[(i + 256) * GHS_STRIDE + bl];
        float r = 1.f / (1.f + expf(-gr));
        float z = 1.f / (1.f + expf(-gz));
        float n = tanhf(gin + r * ghn);
        float h0v = h0sT[i * BPB + bl];
        float hn = (1.f - z) * n + z * h0v;
        g_hnew[b * HID + i]     = hn;
        out_hidden[b * HID + i] = hn;
    }
}

// ---------------------------------------------------------------------------
// Kernel 2: logits = ReLU(h_new @ W_out^T + b_out) via mma.sync tf32
//   Persistent (grid=148), 512 thr / 16 warps, warp grid 4m x 4n, warp 32x32
//   B double-buffered cp.async, used RAW (tf32 HW truncation, no cvt);
//   A staged once per mb as RNA tf32 bits; fragments via ldmatrix.x4,
//   software-pipelined + LDSM/MMA interleave; epilogue before barrier.
// ---------------------------------------------------------------------------
#define TSTR      132                                 // smem row stride (floats)
#define NB        ((VOCAB + 127) / 128)               // 782 n-tiles
#define TILES     (NB * 8)                            // 6256
#define GRID_G    148
#define CHUNK     ((TILES + GRID_G - 1) / GRID_G)     // 43
#define TILE_W    (128 * TSTR)
#define GEMM_SMEM (3 * TILE_W * 4)                    // 202,752 B

__device__ __forceinline__ void mma_tf32(float c[4],
                                         uint32_t a0, uint32_t a1, uint32_t a2, uint32_t a3,
                                         uint32_t b0, uint32_t b1) {
    asm volatile(
        "mma.sync.aligned.m16n8k8.row.col.f32.tf32.tf32.f32 "
        "{%0,%1,%2,%3}, {%4,%5,%6,%7}, {%8,%9}, {%0,%1,%2,%3};"
        : "+f"(c[0]), "+f"(c[1]), "+f"(c[2]), "+f"(c[3])
        : "r"(a0), "r"(a1), "r"(a2), "r"(a3), "r"(b0), "r"(b1));
}

// Prefetch B tile t (raw fp32) into buffer. Always commits a group.
__device__ __forceinline__ void prefetch_B(int t, int t_end,
                                           float* Bbuf, uint32_t Bbuf_a,
                                           const float* __restrict__ Wout, int tid) {
    if (t < t_end) {
        int n0 = (t % NB) * 128;
#pragma unroll
        for (int i = 0; i < 8; i++) {
            int chunk = tid + (i << 9);        // 0..4095
            int r = chunk >> 5;
            int q = chunk & 31;
            int n = n0 + r;
            if (n < VOCAB) {
                cpa16(Bbuf_a + (uint32_t)(r * (TSTR * 4) + q * 16),
                      Wout + (size_t)n * HID + q * 4);
            } else {
                *(float4*)(Bbuf + r * TSTR + q * 4) = make_float4(0.f, 0.f, 0.f, 0.f);
            }
        }
    }
    cpa_commit();
}

__global__ __launch_bounds__(512, 1)
void gemm_out_kernel(const float* __restrict__ Wout,
                     const float* __restrict__ bout,
                     float*       __restrict__ out) {
    extern __shared__ float smf[];
    float* Bb[2] = { smf + TILE_W, smf + 2 * TILE_W };
    uint32_t* As = (uint32_t*)smf;                 // tf32 bits (RNA)
    const uint32_t sbase  = smem_u32(smf);
    const uint32_t Bba[2] = { sbase + TILE_W * 4, sbase + 2 * TILE_W * 4 };

    const int tid = threadIdx.x;
    const int t0  = blockIdx.x * CHUNK;
    if (t0 >= TILES) return;
    const int t1  = min(t0 + CHUNK, TILES);

    const int w    = tid >> 5;
    const int lane = tid & 31;
    const int mw   = w >> 2;        // 0..3
    const int nw   = w & 3;         // 0..3
    const int g    = lane >> 2;     // 0..7
    const int t4   = lane & 3;      // 0..3
    const int lr   = lane & 7;
    const int s1   = (lane >> 3) & 1;
    const int s2   = (lane >> 4) & 1;

    // ldmatrix per-lane addresses
    uint32_t aAdr0 = sbase + 4u * ((mw * 32 +      lr + 8 * s1) * TSTR + 4 * s2);
    uint32_t aAdr1 = sbase + 4u * ((mw * 32 + 16 + lr + 8 * s1) * TSTR + 4 * s2);
    uint32_t bOff0 = 4u * ((nw * 32 + s2 * 8 + lr) * TSTR + 4 * s1);
    uint32_t bOff1 = 4u * ((nw * 32 + (2 + s2) * 8 + lr) * TSTR + 4 * s1);

    // prologue: prefetch first two B tiles
    prefetch_B(t0,     t1, Bb[0], Bba[0], Wout, tid);
    prefetch_B(t0 + 1, t1, Bb[1], Bba[1], Wout, tid);

    int cur    = 0;
    int cur_mb = -1;

    for (int t = t0; t < t1; t++) {
        cpa_wait1();
        __syncthreads();

        const int mb = t / NB;
        const int nb = t % NB;

        if (mb != cur_mb) {     // stage A as RNA tf32 bits (<=2x per CTA)
#pragma unroll
            for (int i = 0; i < 8; i++) {
                int idx = tid + (i << 9);
                int r  = idx >> 5;
                int kq = (idx & 31) << 2;
                float4 a = *(const float4*)(g_hnew + ((size_t)(mb * 128 + r) << 7) + kq);
                *(uint4*)(As + r * TSTR + kq) =
                    make_uint4(f2tf32(a.x), f2tf32(a.y), f2tf32(a.z), f2tf32(a.w));
            }
            cur_mb = mb;
            __syncthreads();
        }

        const uint32_t bAdr0 = Bba[cur] + bOff0;
        const uint32_t bAdr1 = Bba[cur] + bOff1;

        // preload bias into regs: its L2 latency hides under the mainloop
        float2 bias[4];
#pragma unroll
        for (int ni = 0; ni < 4; ni++) {
            int col = nb * 128 + nw * 32 + ni * 8 + 2 * t4;
            bias[ni] = (col < VOCAB) ? __ldg((const float2*)(bout + col))
                                     : make_float2(0.f, 0.f);
        }

        float c[2][4][4];
#pragma unroll
        for (int mi = 0; mi < 2; mi++)
#pragma unroll
            for (int ni = 0; ni < 4; ni++)
#pragma unroll
                for (int q = 0; q < 4; q++) c[mi][ni][q] = 0.f;

        // software-pipelined mainloop, LDSM/MMA interleaved
        uint32_t A0[2][4], A1[2][4], B0[2][4], B1[2][4];
        ldsm4(A0[0], aAdr0);
        ldsm4(A1[0], aAdr1);
        ldsm4(B0[0], bAdr0);
        ldsm4(B1[0], bAdr1);
#pragma unroll
        for (int ks = 0; ks < 16; ks++) {
            const int pb = ks & 1;
            const int nx = pb ^ 1;
            const uint32_t d = (ks + 1) * 32;
            if (ks < 15) {
                ldsm4(A0[nx], aAdr0 + d);
                ldsm4(A1[nx], aAdr1 + d);
            }
            mma_tf32(c[0][0], A0[pb][0], A0[pb][1], A0[pb][2], A0[pb][3], B0[pb][0], B0[pb][1]);
            mma_tf32(c[0][1], A0[pb][0], A0[pb][1], A0[pb][2], A0[pb][3], B0[pb][2], B0[pb][3]);
            mma_tf32(c[1][0], A1[pb][0], A1[pb][1], A1[pb][2], A1[pb][3], B0[pb][0], B0[pb][1]);
            mma_tf32(c[1][1], A1[pb][0], A1[pb][1], A1[pb][2], A1[pb][3], B0[pb][2], B0[pb][3]);
            if (ks < 15) {
                ldsm4(B0[nx], bAdr0 + d);
                ldsm4(B1[nx], bAdr1 + d);
            }
            mma_tf32(c[0][2], A0[pb][0], A0[pb][1], A0[pb][2], A0[pb][3], B1[pb][0], B1[pb][1]);
            mma_tf32(c[0][3], A0[pb][0], A0[pb][1], A0[pb][2], A0[pb][3], B1[pb][2], B1[pb][3]);
            mma_tf32(c[1][2], A1[pb][0], A1[pb][1], A1[pb][2], A1[pb][3], B1[pb][0], B1[pb][1]);
            mma_tf32(c[1][3], A1[pb][0], A1[pb][1], A1[pb][2], A1[pb][3], B1[pb][2], B1[pb][3]);
        }

        // epilogue FIRST (useful work absorbs warp arrival spread), then barrier
#pragma unroll
        for (int mi = 0; mi < 2; mi++) {
            int row0 = mb * 128 + mw * 32 + mi * 16 + g;
            float* d0 = out + (size_t)row0 * VOCAB;
            float* d1 = d0 + 8 * VOCAB;
#pragma unroll
            for (int ni = 0; ni < 4; ni++) {
                int col = nb * 128 + nw * 32 + ni * 8 + 2 * t4;
                if (col < VOCAB) {
                    float2 v0 = make_float2(fmaxf(c[mi][ni][0] + bias[ni].x, 0.f),
                                            fmaxf(c[mi][ni][1] + bias[ni].y, 0.f));
                    float2 v1 = make_float2(fmaxf(c[mi][ni][2] + bias[ni].x, 0.f),
                                            fmaxf(c[mi][ni][3] + bias[ni].y, 0.f));
                    __stcs((float2*)(d0 + col), v0);   // evict-first: keep W_out in L2
                    __stcs((float2*)(d1 + col), v1);
                }
            }
        }

        __syncthreads();        // all warps done reading Bb[cur]
        prefetch_B(t + 2, t1, Bb[cur], Bba[cur], Wout, tid);
        cur ^= 1;
    }
}

// ---------------------------------------------------------------------------
// launch
// ---------------------------------------------------------------------------
extern "C" void kernel_launch(void* const* d_in, const int* in_sizes, int n_in,
                              void* d_out, int out_size) {
    const int*   inp  = (const int*)  d_in[0];
    const float* hid  = (const float*)d_in[1];
    const float* Wih  = (const float*)d_in[2];
    const float* bih  = (const float*)d_in[3];
    const float* Whh  = (const float*)d_in[4];
    const float* bhh  = (const float*)d_in[5];
    const float* Wout = (const float*)d_in[6];
    const float* bout = (const float*)d_in[7];
    float* out = (float*)d_out;

    cudaFuncSetAttribute(gru_kernel, cudaFuncAttributeMaxDynamicSharedMemorySize, GRU_SMEM);
    cudaFuncSetAttribute(gemm_out_kernel, cudaFuncAttributeMaxDynamicSharedMemorySize, GEMM_SMEM);

    // output layout: [logits (1024 x 100000) | hidden (1 x 1024 x 128)]
    gru_kernel<<<BATCH / BPB, GRU_THREADS, GRU_SMEM>>>(
        inp, hid, Wih, bih, Whh, bhh, out + (size_t)BATCH * VOCAB);
    gemm_out_kernel<<<GRID_G, 512, GEMM_SMEM>>>(Wout, bout, out);
}

// round 16
// speedup vs baseline: 1.5858x; 1.0181x over previous
#include <cuda_runtime.h>
#include <cuda_bf16.h>
#include <cstdint>
#include <math.h>

#define VOCAB 100000
#define HID   128
#define BATCH 1024

// intermediate h_new (fp32) between the two kernels
__device__ float g_hnew[BATCH * HID];

__device__ __forceinline__ uint32_t f2tf32(float x) {
    uint32_t r;
    asm("cvt.rna.tf32.f32 %0, %1;" : "=r"(r) : "f"(x));
    return r;
}
__device__ __forceinline__ uint32_t smem_u32(const void* p) {
    uint32_t a;
    asm("{ .reg .u64 t; cvta.to.shared.u64 t, %1; cvt.u32.u64 %0, t; }"
        : "=r"(a) : "l"(p));
    return a;
}
__device__ __forceinline__ void cpa16(uint32_t dst, const void* src) {
    asm volatile("cp.async.cg.shared.global [%0], [%1], 16;"
                 :: "r"(dst), "l"(src) : "memory");
}
__device__ __forceinline__ void cpa_commit() {
    asm volatile("cp.async.commit_group;" ::: "memory");
}
__device__ __forceinline__ void cpa_wait1() {
    asm volatile("cp.async.wait_group 1;" ::: "memory");
}
__device__ __forceinline__ void ldsm4(uint32_t r[4], uint32_t addr) {
    asm volatile("ldmatrix.sync.aligned.m8n8.x4.shared.b16 {%0,%1,%2,%3}, [%4];"
                 : "=r"(r[0]), "=r"(r[1]), "=r"(r[2]), "=r"(r[3]) : "r"(addr));
}

// ---------------------------------------------------------------------------
// Kernel 1: GRU cell -> h_new  (128 CTAs x 384 thr, 8 batches per CTA)
// ---------------------------------------------------------------------------
#define BPB         8
#define GRU_THREADS 384
#define WHS_STRIDE  129
#define GHS_STRIDE  9
#define GRU_SMEM    ((384 * WHS_STRIDE + 128 * BPB) * 4)   // 202,240 B

__global__ __launch_bounds__(GRU_THREADS, 1)
void gru_kernel(const int*   __restrict__ inp,
                const float* __restrict__ hid,
                const float* __restrict__ Wih,
                const float* __restrict__ bih,
                const float* __restrict__ Whh,
                const float* __restrict__ bhh,
                float*       __restrict__ out_hidden) {
    extern __shared__ float sm[];
    float* whs  = sm;                        // [384][129]
    float* h0sT = sm + 384 * WHS_STRIDE;     // [128 k][8 bl]
    float* ghs  = sm;                        // overlay after phase 2: [384][9]

    const int tid = threadIdx.x;
    const int b0  = blockIdx.x * BPB;

#pragma unroll 4
    for (int i = 0; i < 32; i++) {
        int idx = tid + i * GRU_THREADS;
        int j = idx >> 5, kq = (idx & 31) << 2;
        float4 w = *(const float4*)(Whh + j * HID + kq);
        float* d = whs + j * WHS_STRIDE + kq;
        d[0] = w.x; d[1] = w.y; d[2] = w.z; d[3] = w.w;
    }
    for (int idx = tid; idx < BPB * HID; idx += GRU_THREADS) {
        int bl = idx >> 7, k = idx & 127;
        h0sT[k * BPB + bl] = hid[(b0 + bl) * HID + k];
    }
    __syncthreads();

    const int j = tid;                       // 0..383
    float acc[BPB];
    {
        float bb = bhh[j];
#pragma unroll
        for (int u = 0; u < BPB; u++) acc[u] = bb;
        const float* wr = whs + j * WHS_STRIDE;
        for (int k = 0; k < HID; k++) {
            float  w  = wr[k];
            float4 h0 = *(const float4*)(h0sT + k * BPB);
            float4 h1 = *(const float4*)(h0sT + k * BPB + 4);
            acc[0] += h0.x * w;  acc[1] += h0.y * w;
            acc[2] += h0.z * w;  acc[3] += h0.w * w;
            acc[4] += h1.x * w;  acc[5] += h1.y * w;
            acc[6] += h1.z * w;  acc[7] += h1.w * w;
        }
    }
    __syncthreads();
#pragma unroll
    for (int u = 0; u < BPB; u++)
        ghs[j * GHS_STRIDE + u] = acc[u];
    __syncthreads();

    // Phase 3: hoist all scattered W_ih gathers first (MLP 9), then compute.
    float wr_[3], wz_[3], wn_[3];
#pragma unroll
    for (int it = 0; it < 3; it++) {
        int idx = tid + it * GRU_THREADS;
        if (idx < BPB * HID) {
            int bl = idx >> 7, i = idx & 127;
            int v = inp[b0 + bl];
            wr_[it] = Wih[(size_t)i * VOCAB + v];
            wz_[it] = Wih[(size_t)(i + 128) * VOCAB + v];
            wn_[it] = Wih[(size_t)(i + 256) * VOCAB + v];
        }
    }
#pragma unroll
    for (int it = 0; it < 3; it++) {
        int idx = tid + it * GRU_THREADS;
        if (idx < BPB * HID) {
            int bl = idx >> 7, i = idx & 127;
            int b = b0 + bl;
            float gr  = wr_[it] + bih[i]       + ghs[i * GHS_STRIDE + bl];
            float gz  = wz_[it] + bih[i + 128] + ghs[(i + 128) * GHS_STRIDE + bl];
            float gin = wn_[it] + bih[i + 256];
            float ghn = ghs[(i + 256) * GHS_STRIDE + bl];
            float r = 1.f / (1.f + expf(-gr));
            float z = 1.f / (1.f + expf(-gz));
            float n = tanhf(gin + r * ghn);
            float h0v = h0sT[i * BPB + bl];
            float hn = (1.f - z) * n + z * h0v;
            g_hnew[b * HID + i]     = hn;
            out_hidden[b * HID + i] = hn;
        }
    }
}

// ---------------------------------------------------------------------------
// Kernel 2: logits = ReLU(h_new @ W_out^T + b_out) via mma.sync tf32
//   Persistent (grid=148), 512 thr / 16 warps, warp grid 4m x 4n, warp 32x32
//   B double-buffered cp.async, used RAW (tf32 HW truncation, no cvt);
//   A staged once per mb as RNA tf32 bits; fragments via ldmatrix.x4,
//   software-pipelined + LDSM/MMA interleave + PER-WARP K-STAGGER
//   (warps start at different k-phases to de-phase crossbar vs tensor bursts).
// ---------------------------------------------------------------------------
#define TSTR      132                                 // smem row stride (floats)
#define NB        ((VOCAB + 127) / 128)               // 782 n-tiles
#define TILES     (NB * 8)                            // 6256
#define GRID_G    148
#define CHUNK     ((TILES + GRID_G - 1) / GRID_G)     // 43
#define TILE_W    (128 * TSTR)
#define GEMM_SMEM (3 * TILE_W * 4)                    // 202,752 B

__device__ __forceinline__ void mma_tf32(float c[4],
                                         uint32_t a0, uint32_t a1, uint32_t a2, uint32_t a3,
                                         uint32_t b0, uint32_t b1) {
    asm volatile(
        "mma.sync.aligned.m16n8k8.row.col.f32.tf32.tf32.f32 "
        "{%0,%1,%2,%3}, {%4,%5,%6,%7}, {%8,%9}, {%0,%1,%2,%3};"
        : "+f"(c[0]), "+f"(c[1]), "+f"(c[2]), "+f"(c[3])
        : "r"(a0), "r"(a1), "r"(a2), "r"(a3), "r"(b0), "r"(b1));
}

// Prefetch B tile t (raw fp32) into buffer. Always commits a group.
__device__ __forceinline__ void prefetch_B(int t, int t_end,
                                           float* Bbuf, uint32_t Bbuf_a,
                                           const float* __restrict__ Wout, int tid) {
    if (t < t_end) {
        int n0 = (t % NB) * 128;
#pragma unroll
        for (int i = 0; i < 8; i++) {
            int chunk = tid + (i << 9);        // 0..4095
            int r = chunk >> 5;
            int q = chunk & 31;
            int n = n0 + r;
            if (n < VOCAB) {
                cpa16(Bbuf_a + (uint32_t)(r * (TSTR * 4) + q * 16),
                      Wout + (size_t)n * HID + q * 4);
            } else {
                *(float4*)(Bbuf + r * TSTR + q * 4) = make_float4(0.f, 0.f, 0.f, 0.f);
            }
        }
    }
    cpa_commit();
}

__global__ __launch_bounds__(512, 1)
void gemm_out_kernel(const float* __restrict__ Wout,
                     const float* __restrict__ bout,
                     float*       __restrict__ out) {
    extern __shared__ float smf[];
    float* Bb[2] = { smf + TILE_W, smf + 2 * TILE_W };
    uint32_t* As = (uint32_t*)smf;                 // tf32 bits (RNA)
    const uint32_t sbase  = smem_u32(smf);
    const uint32_t Bba[2] = { sbase + TILE_W * 4, sbase + 2 * TILE_W * 4 };

    const int tid = threadIdx.x;
    const int t0  = blockIdx.x * CHUNK;
    if (t0 >= TILES) return;
    const int t1  = min(t0 + CHUNK, TILES);

    const int w    = tid >> 5;
    const int lane = tid & 31;
    const int mw   = w >> 2;        // 0..3
    const int nw   = w & 3;         // 0..3
    const int g    = lane >> 2;     // 0..7
    const int t4   = lane & 3;      // 0..3
    const int lr   = lane & 7;
    const int s1   = (lane >> 3) & 1;
    const int s2   = (lane >> 4) & 1;
    const int ph   = (w & 3) << 2;  // per-warp k-phase: 0,4,8,12

    // ldmatrix per-lane addresses
    uint32_t aAdr0 = sbase + 4u * ((mw * 32 +      lr + 8 * s1) * TSTR + 4 * s2);
    uint32_t aAdr1 = sbase + 4u * ((mw * 32 + 16 + lr + 8 * s1) * TSTR + 4 * s2);
    uint32_t bOff0 = 4u * ((nw * 32 + s2 * 8 + lr) * TSTR + 4 * s1);
    uint32_t bOff1 = 4u * ((nw * 32 + (2 + s2) * 8 + lr) * TSTR + 4 * s1);

    // prologue: prefetch first two B tiles
    prefetch_B(t0,     t1, Bb[0], Bba[0], Wout, tid);
    prefetch_B(t0 + 1, t1, Bb[1], Bba[1], Wout, tid);

    int cur    = 0;
    int cur_mb = -1;

    for (int t = t0; t < t1; t++) {
        cpa_wait1();
        __syncthreads();

        const int mb = t / NB;
        const int nb = t % NB;

        if (mb != cur_mb) {     // stage A as RNA tf32 bits (<=2x per CTA)
#pragma unroll
            for (int i = 0; i < 8; i++) {
                int idx = tid + (i << 9);
                int r  = idx >> 5;
                int kq = (idx & 31) << 2;
                float4 a = *(const float4*)(g_hnew + ((size_t)(mb * 128 + r) << 7) + kq);
                *(uint4*)(As + r * TSTR + kq) =
                    make_uint4(f2tf32(a.x), f2tf32(a.y), f2tf32(a.z), f2tf32(a.w));
            }
            cur_mb = mb;
            __syncthreads();
        }

        const uint32_t bAdr0 = Bba[cur] + bOff0;
        const uint32_t bAdr1 = Bba[cur] + bOff1;

        // bias preload FIRST: its L2 latency hides under pipeline fill+mainloop
        float2 bias[4];
#pragma unroll
        for (int ni = 0; ni < 4; ni++) {
            int col = nb * 128 + nw * 32 + ni * 8 + 2 * t4;
            bias[ni] = (col < VOCAB) ? __ldg((const float2*)(bout + col))
                                     : make_float2(0.f, 0.f);
        }

        float c[2][4][4];
#pragma unroll
        for (int mi = 0; mi < 2; mi++)
#pragma unroll
            for (int ni = 0; ni < 4; ni++)
#pragma unroll
                for (int q = 0; q < 4; q++) c[mi][ni][q] = 0.f;

        // software-pipelined mainloop, LDSM/MMA interleaved, k staggered by ph
        uint32_t A0[2][4], A1[2][4], B0[2][4], B1[2][4];
        {
            const uint32_t d0 = (uint32_t)(ph * 32);
            ldsm4(A0[0], aAdr0 + d0);
            ldsm4(A1[0], aAdr1 + d0);
            ldsm4(B0[0], bAdr0 + d0);
            ldsm4(B1[0], bAdr1 + d0);
        }
#pragma unroll
        for (int ks = 0; ks < 16; ks++) {
            const int pb = ks & 1;
            const int nx = pb ^ 1;
            const uint32_t d = (uint32_t)(((ks + 1 + ph) & 15) * 32);
            if (ks < 15) {
                ldsm4(A0[nx], aAdr0 + d);
                ldsm4(A1[nx], aAdr1 + d);
            }
            mma_tf32(c[0][0], A0[pb][0], A0[pb][1], A0[pb][2], A0[pb][3], B0[pb][0], B0[pb][1]);
            mma_tf32(c[0][1], A0[pb][0], A0[pb][1], A0[pb][2], A0[pb][3], B0[pb][2], B0[pb][3]);
            mma_tf32(c[1][0], A1[pb][0], A1[pb][1], A1[pb][2], A1[pb][3], B0[pb][0], B0[pb][1]);
            mma_tf32(c[1][1], A1[pb][0], A1[pb][1], A1[pb][2], A1[pb][3], B0[pb][2], B0[pb][3]);
            if (ks < 15) {
                ldsm4(B0[nx], bAdr0 + d);
                ldsm4(B1[nx], bAdr1 + d);
            }
            mma_tf32(c[0][2], A0[pb][0], A0[pb][1], A0[pb][2], A0[pb][3], B1[pb][0], B1[pb][1]);
            mma_tf32(c[0][3], A0[pb][0], A0[pb][1], A0[pb][2], A0[pb][3], B1[pb][2], B1[pb][3]);
            mma_tf32(c[1][2], A1[pb][0], A1[pb][1], A1[pb][2], A1[pb][3], B1[pb][0], B1[pb][1]);
            mma_tf32(c[1][3], A1[pb][0], A1[pb][1], A1[pb][2], A1[pb][3], B1[pb][2], B1[pb][3]);
        }

        // epilogue before barrier (absorbs warp arrival spread)
#pragma unroll
        for (int mi = 0; mi < 2; mi++) {
            int row0 = mb * 128 + mw * 32 + mi * 16 + g;
            float* d0 = out + (size_t)row0 * VOCAB;
            float* d1 = d0 + 8 * VOCAB;
#pragma unroll
            for (int ni = 0; ni < 4; ni++) {
                int col = nb * 128 + nw * 32 + ni * 8 + 2 * t4;
                if (col < VOCAB) {
                    float2 v0 = make_float2(fmaxf(c[mi][ni][0] + bias[ni].x, 0.f),
                                            fmaxf(c[mi][ni][1] + bias[ni].y, 0.f));
                    float2 v1 = make_float2(fmaxf(c[mi][ni][2] + bias[ni].x, 0.f),
                                            fmaxf(c[mi][ni][3] + bias[ni].y, 0.f));
                    __stcs((float2*)(d0 + col), v0);   // evict-first: keep W_out in L2
                    __stcs((float2*)(d1 + col), v1);
                }
            }
        }

        __syncthreads();        // all warps done reading Bb[cur]
        prefetch_B(t + 2, t1, Bb[cur], Bba[cur], Wout, tid);
        cur ^= 1;
    }
}

// ---------------------------------------------------------------------------
// launch
// ---------------------------------------------------------------------------
extern "C" void kernel_launch(void* const* d_in, const int* in_sizes, int n_in,
                              void* d_out, int out_size) {
    const int*   inp  = (const int*)  d_in[0];
    const float* hid  = (const float*)d_in[1];
    const float* Wih  = (const float*)d_in[2];
    const float* bih  = (const float*)d_in[3];
    const float* Whh  = (const float*)d_in[4];
    const float* bhh  = (const float*)d_in[5];
    const float* Wout = (const float*)d_in[6];
    const float* bout = (const float*)d_in[7];
    float* out = (float*)d_out;

    cudaFuncSetAttribute(gru_kernel, cudaFuncAttributeMaxDynamicSharedMemorySize, GRU_SMEM);
    cudaFuncSetAttribute(gemm_out_kernel, cudaFuncAttributeMaxDynamicSharedMemorySize, GEMM_SMEM);

    // output layout: [logits (1024 x 100000) | hidden (1 x 1024 x 128)]
    gru_kernel<<<BATCH / BPB, GRU_THREADS, GRU_SMEM>>>(
        inp, hid, Wih, bih, Whh, bhh, out + (size_t)BATCH * VOCAB);
    gemm_out_kernel<<<GRID_G, 512, GEMM_SMEM>>>(Wout, bout, out);
}